// round 2
// baseline (speedup 1.0000x reference)
#include <cuda_runtime.h>

// out[n] = realism(std(chunks[n])) + 0.3*0.5 + 0.2*cos(chunks[n,:10,:], prev[-10:,:])
//
// chunks: [4096, 128, 64] f32  -> 8192 floats per chunk = 2048 float4
// prev:   [128, 64] f32, ctx = last 10 rows = 640 floats (offset 7552, 16B aligned)
// out:    [4096] f32

__global__ __launch_bounds__(256) void chunk_ranker_kernel(
    const float4* __restrict__ chunks4,
    const float* __restrict__ prev,
    float* __restrict__ out)
{
    const int n = blockIdx.x;
    const int t = threadIdx.x;
    const float4* base = chunks4 + (size_t)n * 2048;
    const float4* ctx4 = reinterpret_cast<const float4*>(prev + 118 * 64); // 640 floats = 160 float4

    float sum = 0.f, sq = 0.f, dot = 0.f, ssq = 0.f, csq = 0.f;

    // Iteration i=0 covers float4 indices [0,256): only j<160 touches the prefix.
    {
        float4 v = base[t];
        sum += v.x + v.y + v.z + v.w;
        sq  += v.x*v.x + v.y*v.y + v.z*v.z + v.w*v.w;
        if (t < 160) {
            float4 c = __ldg(&ctx4[t]);
            dot += v.x*c.x + v.y*c.y + v.z*c.z + v.w*c.w;
            ssq += v.x*v.x + v.y*v.y + v.z*v.z + v.w*v.w;
            csq += c.x*c.x + c.y*c.y + c.z*c.z + c.w*c.w;
        }
    }
    #pragma unroll
    for (int i = 1; i < 8; i++) {
        float4 v = base[t + 256 * i];
        sum += v.x + v.y + v.z + v.w;
        sq  += v.x*v.x + v.y*v.y + v.z*v.z + v.w*v.w;
    }

    // Warp reduction of 5 quantities
    #pragma unroll
    for (int off = 16; off > 0; off >>= 1) {
        sum += __shfl_down_sync(0xffffffffu, sum, off);
        sq  += __shfl_down_sync(0xffffffffu, sq,  off);
        dot += __shfl_down_sync(0xffffffffu, dot, off);
        ssq += __shfl_down_sync(0xffffffffu, ssq, off);
        csq += __shfl_down_sync(0xffffffffu, csq, off);
    }

    __shared__ float red[8][5];
    const int wid = t >> 5, lid = t & 31;
    if (lid == 0) {
        red[wid][0] = sum; red[wid][1] = sq; red[wid][2] = dot;
        red[wid][3] = ssq; red[wid][4] = csq;
    }
    __syncthreads();

    if (t == 0) {
        float S = 0.f, Q = 0.f, D = 0.f, SS = 0.f, CS = 0.f;
        #pragma unroll
        for (int w = 0; w < 8; w++) {
            S += red[w][0]; Q += red[w][1]; D += red[w][2];
            SS += red[w][3]; CS += red[w][4];
        }
        const float M = 8192.0f;
        float var = (Q - S * S / M) / (M - 1.0f);
        float std = sqrtf(fmaxf(var, 0.0f));

        float realism;
        if (std < 0.01f)      realism = std * 10.0f;
        else if (std > 0.5f)  realism = 0.5f / std;
        else                  realism = 1.0f - fabsf(std - 0.1f);

        float denom = fmaxf(sqrtf(SS) * sqrtf(CS), 1e-8f);
        float boundary = D / denom;

        out[n] = realism + 0.3f * 0.5f + 0.2f * boundary;
    }
}

extern "C" void kernel_launch(void* const* d_in, const int* in_sizes, int n_in,
                              void* d_out, int out_size)
{
    const float4* chunks4 = (const float4*)d_in[0];   // [4096,128,64] f32
    // d_in[1] = regime_probs [9] — unused (constant consistency 0.5)
    const float* prev = (const float*)d_in[2];        // [128,64] f32
    float* out = (float*)d_out;                       // [4096] f32

    const int n_chunks = in_sizes[0] / (128 * 64);    // 4096
    chunk_ranker_kernel<<<n_chunks, 256>>>(chunks4, prev, out);
}